// round 1
// baseline (speedup 1.0000x reference)
#include <cuda_runtime.h>
#include <math.h>

#define SN 6400
#define CC 256
#define NBATCH 2

// ---------------- scratch (device globals; no allocation allowed) ----------
__device__ float    g_A[NBATCH * SN * CC];                 // normalized I, [n][s][c]
__device__ float    g_Bm[NBATCH * SN * CC];                // normalized T, [n][s][c]
__device__ float    g_raw[(size_t)NBATCH * SN * SN];       // raw distance matrix
__device__ float    g_mean[CC];
__device__ float2   g_coef[NBATCH * SN];                   // per-row (a_i, c_i)
__device__ unsigned g_colmax[NBATCH * SN];                 // encoded float max

// order-preserving float <-> uint encoding (for atomicMax on signed floats)
__device__ __forceinline__ unsigned enc_f(float f) {
    unsigned u = __float_as_uint(f);
    return (u & 0x80000000u) ? ~u : (u | 0x80000000u);
}
__device__ __forceinline__ float dec_f(unsigned u) {
    u = (u & 0x80000000u) ? (u ^ 0x80000000u) : ~u;
    return __uint_as_float(u);
}

// ---------------- kernel 1: per-channel mean of T over (n,h,w) -------------
__global__ void k_mean(const float* __restrict__ T) {
    int c = blockIdx.x;
    float s = 0.f;
    const float* p0 = T + (size_t)c * SN;
    const float* p1 = T + (size_t)(CC + c) * SN;
    for (int idx = threadIdx.x; idx < SN; idx += 256) s += p0[idx] + p1[idx];
    __shared__ float sh[256];
    sh[threadIdx.x] = s;
    __syncthreads();
    for (int o = 128; o > 0; o >>= 1) {
        if (threadIdx.x < o) sh[threadIdx.x] += sh[threadIdx.x + o];
        __syncthreads();
    }
    if (threadIdx.x == 0) g_mean[c] = sh[0] * (1.f / (NBATCH * SN));
}

// ---------------- kernel 2: center by mean_T, L2-normalize over channels ---
// block = one (n, s) position; thread = channel
__global__ void __launch_bounds__(256) k_norm(const float* __restrict__ I,
                                              const float* __restrict__ T) {
    int b = blockIdx.x;
    int n = b / SN;
    int s = b - n * SN;
    int c = threadIdx.x;
    float m  = g_mean[c];
    float iv = I[((size_t)n * CC + c) * SN + s] - m;
    float tv = T[((size_t)n * CC + c) * SN + s] - m;
    __shared__ float2 sh[256];
    sh[c] = make_float2(iv * iv, tv * tv);
    __syncthreads();
    for (int o = 128; o > 0; o >>= 1) {
        if (c < o) { sh[c].x += sh[c + o].x; sh[c].y += sh[c + o].y; }
        __syncthreads();
    }
    float ri = rsqrtf(sh[0].x);
    float rt = rsqrtf(sh[0].y);
    g_A [((size_t)n * SN + s) * CC + c] = iv * ri;
    g_Bm[((size_t)n * SN + s) * CC + c] = tv * rt;
}

// ---------------- kernel 3: SGEMM  raw = clip((1 - A·B^T)/2, 0) ------------
#define BM 128
#define BN 128
#define BK 8

__global__ void __launch_bounds__(256) k_gemm() {
    int n  = blockIdx.z;
    int i0 = blockIdx.y * BM;
    int j0 = blockIdx.x * BN;
    const float* Ab = g_A  + (size_t)n * SN * CC;
    const float* Bb = g_Bm + (size_t)n * SN * CC;

    __shared__ float As[BK][BM];
    __shared__ float Bs[BK][BN];

    int tid  = threadIdx.x;
    int lrow = tid >> 1;          // 0..127
    int lk   = (tid & 1) * 4;     // 0 or 4
    int tx   = tid & 15;          // j group
    int ty   = tid >> 4;          // i group

    float acc[8][8];
#pragma unroll
    for (int r = 0; r < 8; r++)
#pragma unroll
        for (int c = 0; c < 8; c++) acc[r][c] = 0.f;

    for (int k0 = 0; k0 < CC; k0 += BK) {
        float4 av = *(const float4*)(Ab + (size_t)(i0 + lrow) * CC + k0 + lk);
        float4 bv = *(const float4*)(Bb + (size_t)(j0 + lrow) * CC + k0 + lk);
        __syncthreads();
        As[lk + 0][lrow] = av.x; As[lk + 1][lrow] = av.y;
        As[lk + 2][lrow] = av.z; As[lk + 3][lrow] = av.w;
        Bs[lk + 0][lrow] = bv.x; Bs[lk + 1][lrow] = bv.y;
        Bs[lk + 2][lrow] = bv.z; Bs[lk + 3][lrow] = bv.w;
        __syncthreads();
#pragma unroll
        for (int kk = 0; kk < BK; kk++) {
            float4 a0 = *(const float4*)&As[kk][ty * 8];
            float4 a1 = *(const float4*)&As[kk][ty * 8 + 4];
            float4 b0 = *(const float4*)&Bs[kk][tx * 8];
            float4 b1 = *(const float4*)&Bs[kk][tx * 8 + 4];
            float a[8] = {a0.x, a0.y, a0.z, a0.w, a1.x, a1.y, a1.z, a1.w};
            float bb[8] = {b0.x, b0.y, b0.z, b0.w, b1.x, b1.y, b1.z, b1.w};
#pragma unroll
            for (int r = 0; r < 8; r++)
#pragma unroll
                for (int c = 0; c < 8; c++) acc[r][c] = fmaf(a[r], bb[c], acc[r][c]);
        }
    }

    float* out = g_raw + (size_t)n * SN * SN;
#pragma unroll
    for (int r = 0; r < 8; r++) {
        int i = i0 + ty * 8 + r;
        float4 v0, v1;
        v0.x = fmaxf(0.5f * (1.f - acc[r][0]), 0.f);
        v0.y = fmaxf(0.5f * (1.f - acc[r][1]), 0.f);
        v0.z = fmaxf(0.5f * (1.f - acc[r][2]), 0.f);
        v0.w = fmaxf(0.5f * (1.f - acc[r][3]), 0.f);
        v1.x = fmaxf(0.5f * (1.f - acc[r][4]), 0.f);
        v1.y = fmaxf(0.5f * (1.f - acc[r][5]), 0.f);
        v1.z = fmaxf(0.5f * (1.f - acc[r][6]), 0.f);
        v1.w = fmaxf(0.5f * (1.f - acc[r][7]), 0.f);
        *(float4*)(out + (size_t)i * SN + j0 + tx * 8)     = v0;
        *(float4*)(out + (size_t)i * SN + j0 + tx * 8 + 4) = v1;
    }
}

// ---------------- kernel 4: per-row min + exp-sum -> (a_i, c_i) ------------
// a_i = 10/(rmin+eps), c_i = 10 - ln(Z_i); cs[i,j] = exp(c_i - a_i*raw[i,j])
__global__ void __launch_bounds__(256) k_rowstats() {
    int b = blockIdx.x;               // n*SN + i
    const float* row = g_raw + (size_t)b * SN;
    __shared__ float sh[SN];          // 25.6 KB row cache
    __shared__ float red[256];
    int tid = threadIdx.x;

    float mn = 1e30f;
    for (int j = tid; j < SN; j += 256) {
        float v = row[j];
        sh[j] = v;
        mn = fminf(mn, v);
    }
    red[tid] = mn;
    __syncthreads();
    for (int o = 128; o > 0; o >>= 1) {
        if (tid < o) red[tid] = fminf(red[tid], red[tid + o]);
        __syncthreads();
    }
    float rmin  = red[0];
    float a10   = 10.f / (rmin + 1e-5f);
    __syncthreads();

    float z = 0.f;
    for (int j = tid; j < SN; j += 256) z += __expf(10.f - a10 * sh[j]);
    red[tid] = z;
    __syncthreads();
    for (int o = 128; o > 0; o >>= 1) {
        if (tid < o) red[tid] += red[tid + o];
        __syncthreads();
    }
    if (tid == 0) g_coef[b] = make_float2(a10, 10.f - __logf(red[0]));
}

// ---------------- kernel 5a: init colmax ----------------------------------
__global__ void k_init_colmax() {
    int idx = blockIdx.x * 256 + threadIdx.x;
    if (idx < NBATCH * SN) g_colmax[idx] = enc_f(-1e30f);
}

// ---------------- kernel 5b: column max of t = c_i - a_i*raw --------------
#define ICH 640
__global__ void __launch_bounds__(256) k_colmax() {
    int n  = blockIdx.z;
    int j  = blockIdx.x * 256 + threadIdx.x;
    int ib = blockIdx.y * ICH;

    __shared__ float2 cf[ICH];
    for (int q = threadIdx.x; q < ICH; q += 256) cf[q] = g_coef[n * SN + ib + q];
    __syncthreads();

    const float* base = g_raw + (size_t)n * SN * SN + (size_t)ib * SN + j;
    float m = -1e30f;
#pragma unroll 4
    for (int q = 0; q < ICH; q++) {
        float v  = base[(size_t)q * SN];
        float2 c = cf[q];
        m = fmaxf(m, c.y - c.x * v);
    }
    atomicMax(&g_colmax[n * SN + j], enc_f(m));
}

// ---------------- kernel 6: final reduction -> loss ------------------------
__global__ void k_final(float* __restrict__ out) {
    __shared__ float2 sh[256];
    int tid = threadIdx.x;
    float s0 = 0.f, s1 = 0.f;
    for (int j = tid; j < SN; j += 256) {
        s0 += __expf(dec_f(g_colmax[j]));
        s1 += __expf(dec_f(g_colmax[SN + j]));
    }
    sh[tid] = make_float2(s0, s1);
    __syncthreads();
    for (int o = 128; o > 0; o >>= 1) {
        if (tid < o) { sh[tid].x += sh[tid + o].x; sh[tid].y += sh[tid + o].y; }
        __syncthreads();
    }
    if (tid == 0) {
        float cs0 = sh[0].x * (1.f / SN);
        float cs1 = sh[0].y * (1.f / SN);
        out[0] = -0.5f * (logf(cs0) + logf(cs1));
    }
}

// ---------------- launcher --------------------------------------------------
extern "C" void kernel_launch(void* const* d_in, const int* in_sizes, int n_in,
                              void* d_out, int out_size) {
    const float* I = (const float*)d_in[0];
    const float* T = (const float*)d_in[1];
    float* out = (float*)d_out;

    k_mean<<<CC, 256>>>(T);
    k_norm<<<NBATCH * SN, 256>>>(I, T);
    dim3 gg(SN / BN, SN / BM, NBATCH);
    k_gemm<<<gg, 256>>>();
    k_init_colmax<<<(NBATCH * SN + 255) / 256, 256>>>();
    k_rowstats<<<NBATCH * SN, 256>>>();
    k_colmax<<<dim3(SN / 256, SN / ICH, NBATCH), 256>>>();
    k_final<<<1, 256>>>(out);
}

// round 3
// speedup vs baseline: 2.1884x; 2.1884x over previous
#include <cuda_runtime.h>
#include <cuda_bf16.h>
#include <math.h>
#include <stdint.h>

#define SN 6400
#define CC 256
#define NBATCH 2

// ---------------- scratch (device globals; no allocation allowed) ----------
__device__ __align__(16) __nv_bfloat16 g_Ahi[NBATCH * SN * CC];
__device__ __align__(16) __nv_bfloat16 g_Alo[NBATCH * SN * CC];
__device__ __align__(16) __nv_bfloat16 g_Bhi[NBATCH * SN * CC];
__device__ __align__(16) __nv_bfloat16 g_Blo[NBATCH * SN * CC];
__device__ float    g_raw[(size_t)NBATCH * SN * SN];       // raw distance matrix
__device__ float    g_mean[CC];
__device__ float2   g_coef[NBATCH * SN];                   // per-row (a_i, c_i)
__device__ unsigned g_colmax[NBATCH * SN];                 // encoded float max

// order-preserving float <-> uint encoding (atomicMax on floats)
__device__ __forceinline__ unsigned enc_f(float f) {
    unsigned u = __float_as_uint(f);
    return (u & 0x80000000u) ? ~u : (u | 0x80000000u);
}
__device__ __forceinline__ float dec_f(unsigned u) {
    u = (u & 0x80000000u) ? (u ^ 0x80000000u) : ~u;
    return __uint_as_float(u);
}

// ---------------- PTX helpers (plain sm_80-era, no arch-variant gating) ----
__device__ __forceinline__ uint32_t smem_u32(const void* p) {
    uint32_t a;
    asm("{ .reg .u64 t; cvta.to.shared.u64 t, %1; cvt.u32.u64 %0, t; }" : "=r"(a) : "l"(p));
    return a;
}
__device__ __forceinline__ void cp16(uint32_t dst, const void* src) {
    asm volatile("cp.async.cg.shared.global [%0], [%1], 16;" :: "r"(dst), "l"(src));
}
#define CP_COMMIT() asm volatile("cp.async.commit_group;" ::: "memory")
#define CP_WAIT1()  asm volatile("cp.async.wait_group 1;" ::: "memory")

__device__ __forceinline__ void ldsm4(uint32_t r[4], uint32_t a) {
    asm volatile("ldmatrix.sync.aligned.m8n8.x4.shared.b16 {%0,%1,%2,%3}, [%4];"
        : "=r"(r[0]), "=r"(r[1]), "=r"(r[2]), "=r"(r[3]) : "r"(a));
}
__device__ __forceinline__ void mma_bf16(float d[4], const uint32_t a[4],
                                         uint32_t b0, uint32_t b1) {
    asm volatile("mma.sync.aligned.m16n8k16.row.col.f32.bf16.bf16.f32 "
        "{%0,%1,%2,%3}, {%4,%5,%6,%7}, {%8,%9}, {%0,%1,%2,%3};"
        : "+f"(d[0]), "+f"(d[1]), "+f"(d[2]), "+f"(d[3])
        : "r"(a[0]), "r"(a[1]), "r"(a[2]), "r"(a[3]), "r"(b0), "r"(b1));
}
// xor swizzle for 64B rows: bits[5:4] ^= bits[8:7]  (conflict-free ldmatrix)
__device__ __forceinline__ uint32_t sw(uint32_t o) {
    return o ^ (((o >> 7) & 3u) << 4);
}

// ---------------- kernel 1: per-channel mean of T over (n,h,w) -------------
__global__ void k_mean(const float* __restrict__ T) {
    int c = blockIdx.x;
    float s = 0.f;
    const float* p0 = T + (size_t)c * SN;
    const float* p1 = T + (size_t)(CC + c) * SN;
    for (int idx = threadIdx.x; idx < SN; idx += 256) s += p0[idx] + p1[idx];
    __shared__ float sh[256];
    sh[threadIdx.x] = s;
    __syncthreads();
    for (int o = 128; o > 0; o >>= 1) {
        if (threadIdx.x < o) sh[threadIdx.x] += sh[threadIdx.x + o];
        __syncthreads();
    }
    if (threadIdx.x == 0) g_mean[c] = sh[0] * (1.f / (NBATCH * SN));
}

// ---------------- kernel 2: center, L2-normalize, split into bf16 hi/lo ----
__global__ void __launch_bounds__(256) k_norm(const float* __restrict__ I,
                                              const float* __restrict__ T) {
    int b = blockIdx.x;
    int n = b / SN;
    int s = b - n * SN;
    int c = threadIdx.x;
    float m  = g_mean[c];
    float iv = I[((size_t)n * CC + c) * SN + s] - m;
    float tv = T[((size_t)n * CC + c) * SN + s] - m;
    __shared__ float2 sh[256];
    sh[c] = make_float2(iv * iv, tv * tv);
    __syncthreads();
    for (int o = 128; o > 0; o >>= 1) {
        if (c < o) { sh[c].x += sh[c + o].x; sh[c].y += sh[c + o].y; }
        __syncthreads();
    }
    float ri = rsqrtf(sh[0].x);
    float rt = rsqrtf(sh[0].y);
    float x = iv * ri;
    float y = tv * rt;
    size_t idx = ((size_t)n * SN + s) * CC + c;
    __nv_bfloat16 xh = __float2bfloat16(x);
    __nv_bfloat16 yh = __float2bfloat16(y);
    g_Ahi[idx] = xh;
    g_Alo[idx] = __float2bfloat16(x - __bfloat162float(xh));
    g_Bhi[idx] = yh;
    g_Blo[idx] = __float2bfloat16(y - __bfloat162float(yh));
}

// ---------------- kernel 3: mma.sync GEMM  raw = clip((1 - A·B^T)/2, 0) ----
// CTA tile 128x128, K chunks of 32 bf16, split-bf16 3-term, double-buffered.
// smem: stage s (0/1), tile t (0 Ahi, 1 Alo, 2 Bhi, 3 Blo), each 8192 B.
#define TILE_B 8192
#define STAGE_B (4 * TILE_B)
#define GEMM_SMEM (2 * STAGE_B)

__global__ void __launch_bounds__(256, 2) k_gemm_mma() {
    extern __shared__ __align__(1024) char smb[];
    int tid = threadIdx.x;
    int wid = tid >> 5;
    int l   = tid & 31;
    int n  = blockIdx.z;
    int i0 = blockIdx.y * 128;
    int j0 = blockIdx.x * 128;
    uint32_t sbase = smem_u32(smb);

    // ---- per-thread gmem/smem load coords (16B granules) ----
    auto load_stage = [&](int kc, int s) {
        int k0 = kc * 32;
        uint32_t b = sbase + s * STAGE_B;
#pragma unroll
        for (int i = 0; i < 2; i++) {
            int e   = tid + i * 256;
            int row = e >> 2;
            int ch  = e & 3;
            uint32_t so = sw((uint32_t)(row * 64 + ch * 16));
            size_t ga = (size_t)(n * SN + i0 + row) * CC + k0 + ch * 8;
            size_t gb = (size_t)(n * SN + j0 + row) * CC + k0 + ch * 8;
            cp16(b + 0 * TILE_B + so, g_Ahi + ga);
            cp16(b + 1 * TILE_B + so, g_Alo + ga);
            cp16(b + 2 * TILE_B + so, g_Bhi + gb);
            cp16(b + 3 * TILE_B + so, g_Blo + gb);
        }
        CP_COMMIT();
    };

    float acc[2][8][4];
#pragma unroll
    for (int a = 0; a < 2; a++)
#pragma unroll
        for (int g = 0; g < 8; g++)
#pragma unroll
            for (int q = 0; q < 4; q++) acc[a][g][q] = 0.f;

    int wm = wid >> 1;          // 0..3
    int wn = wid & 1;           // 0..1
    int mb = wm * 32;
    int nb = wn * 64;

    int a_row0 = mb + (l & 15);            // + mt*16
    int a_ch   = l >> 4;                   // k-half select
    int b_ch   = (l >> 3) & 1;
    int b_rowq = nb + (l & 7) + ((l >> 4) << 3);  // + ng*16

    load_stage(0, 0);
    load_stage(1, 1);

    for (int kc = 0; kc < 8; kc++) {
        CP_WAIT1();
        __syncthreads();
        uint32_t b = sbase + (kc & 1) * STAGE_B;
#pragma unroll
        for (int ks = 0; ks < 2; ks++) {
            uint32_t ah[2][4], al[2][4], bt[4][4];
#pragma unroll
            for (int mt = 0; mt < 2; mt++) {
                uint32_t off = sw((uint32_t)((a_row0 + mt * 16) * 64 + (ks * 2 + a_ch) * 16));
                ldsm4(ah[mt], b + 0 * TILE_B + off);
                ldsm4(al[mt], b + 1 * TILE_B + off);
            }
#pragma unroll
            for (int ng = 0; ng < 4; ng++) {
                uint32_t off = sw((uint32_t)((b_rowq + ng * 16) * 64 + (ks * 2 + b_ch) * 16));
                ldsm4(bt[ng], b + 2 * TILE_B + off);
            }
#pragma unroll
            for (int mt = 0; mt < 2; mt++)
#pragma unroll
                for (int ng = 0; ng < 4; ng++) {
                    mma_bf16(acc[mt][2 * ng],     ah[mt], bt[ng][0], bt[ng][1]);
                    mma_bf16(acc[mt][2 * ng + 1], ah[mt], bt[ng][2], bt[ng][3]);
                    mma_bf16(acc[mt][2 * ng],     al[mt], bt[ng][0], bt[ng][1]);
                    mma_bf16(acc[mt][2 * ng + 1], al[mt], bt[ng][2], bt[ng][3]);
                }
#pragma unroll
            for (int ng = 0; ng < 4; ng++) {
                uint32_t off = sw((uint32_t)((b_rowq + ng * 16) * 64 + (ks * 2 + b_ch) * 16));
                ldsm4(bt[ng], b + 3 * TILE_B + off);
            }
#pragma unroll
            for (int mt = 0; mt < 2; mt++)
#pragma unroll
                for (int ng = 0; ng < 4; ng++) {
                    mma_bf16(acc[mt][2 * ng],     ah[mt], bt[ng][0], bt[ng][1]);
                    mma_bf16(acc[mt][2 * ng + 1], ah[mt], bt[ng][2], bt[ng][3]);
                }
        }
        __syncthreads();
        if (kc + 2 < 8) load_stage(kc + 2, kc & 1);
        else            CP_COMMIT();
    }

    // ---- epilogue: raw = clip((1-cos)/2, 0) ----
    float* out = g_raw + (size_t)n * SN * SN;
    int r0 = i0 + mb + (l >> 2);
    int c0 = j0 + nb + (l & 3) * 2;
#pragma unroll
    for (int mt = 0; mt < 2; mt++)
#pragma unroll
        for (int g = 0; g < 8; g++) {
            int r = r0 + mt * 16;
            int c = c0 + g * 8;
            float2 v0, v1;
            v0.x = fmaxf(0.5f * (1.f - acc[mt][g][0]), 0.f);
            v0.y = fmaxf(0.5f * (1.f - acc[mt][g][1]), 0.f);
            v1.x = fmaxf(0.5f * (1.f - acc[mt][g][2]), 0.f);
            v1.y = fmaxf(0.5f * (1.f - acc[mt][g][3]), 0.f);
            *(float2*)(out + (size_t)r * SN + c)       = v0;
            *(float2*)(out + (size_t)(r + 8) * SN + c) = v1;
        }
}

// ---------------- kernel 4: per-row min + exp-sum -> (a_i, c_i) ------------
__global__ void __launch_bounds__(256) k_rowstats() {
    int b = blockIdx.x;               // n*SN + i
    const float* row = g_raw + (size_t)b * SN;
    __shared__ float sh[SN];          // 25.6 KB row cache
    __shared__ float red[256];
    int tid = threadIdx.x;

    float mn = 1e30f;
    for (int j = tid; j < SN; j += 256) {
        float v = row[j];
        sh[j] = v;
        mn = fminf(mn, v);
    }
    red[tid] = mn;
    __syncthreads();
    for (int o = 128; o > 0; o >>= 1) {
        if (tid < o) red[tid] = fminf(red[tid], red[tid + o]);
        __syncthreads();
    }
    float rmin = red[0];
    float a10  = 10.f / (rmin + 1e-5f);
    __syncthreads();

    float z = 0.f;
    for (int j = tid; j < SN; j += 256) z += __expf(10.f - a10 * sh[j]);
    red[tid] = z;
    __syncthreads();
    for (int o = 128; o > 0; o >>= 1) {
        if (tid < o) red[tid] += red[tid + o];
        __syncthreads();
    }
    if (tid == 0) g_coef[b] = make_float2(a10, 10.f - __logf(red[0]));
}

// ---------------- kernel 5a: init colmax ----------------------------------
__global__ void k_init_colmax() {
    int idx = blockIdx.x * 256 + threadIdx.x;
    if (idx < NBATCH * SN) g_colmax[idx] = enc_f(-1e30f);
}

// ---------------- kernel 5b: column max of t = c_i - a_i*raw --------------
#define ICH 640
__global__ void __launch_bounds__(256) k_colmax() {
    int n  = blockIdx.z;
    int j  = blockIdx.x * 256 + threadIdx.x;
    int ib = blockIdx.y * ICH;

    __shared__ float2 cf[ICH];
    for (int q = threadIdx.x; q < ICH; q += 256) cf[q] = g_coef[n * SN + ib + q];
    __syncthreads();

    const float* base = g_raw + (size_t)n * SN * SN + (size_t)ib * SN + j;
    float m = -1e30f;
#pragma unroll 4
    for (int q = 0; q < ICH; q++) {
        float v  = base[(size_t)q * SN];
        float2 c = cf[q];
        m = fmaxf(m, c.y - c.x * v);
    }
    atomicMax(&g_colmax[n * SN + j], enc_f(m));
}

// ---------------- kernel 6: final reduction -> loss ------------------------
__global__ void k_final(float* __restrict__ out) {
    __shared__ float2 sh[256];
    int tid = threadIdx.x;
    float s0 = 0.f, s1 = 0.f;
    for (int j = tid; j < SN; j += 256) {
        s0 += __expf(dec_f(g_colmax[j]));
        s1 += __expf(dec_f(g_colmax[SN + j]));
    }
    sh[tid] = make_float2(s0, s1);
    __syncthreads();
    for (int o = 128; o > 0; o >>= 1) {
        if (tid < o) { sh[tid].x += sh[tid + o].x; sh[tid].y += sh[tid + o].y; }
        __syncthreads();
    }
    if (tid == 0) {
        float cs0 = sh[0].x * (1.f / SN);
        float cs1 = sh[0].y * (1.f / SN);
        out[0] = -0.5f * (logf(cs0) + logf(cs1));
    }
}

// ---------------- launcher --------------------------------------------------
extern "C" void kernel_launch(void* const* d_in, const int* in_sizes, int n_in,
                              void* d_out, int out_size) {
    const float* I = (const float*)d_in[0];
    const float* T = (const float*)d_in[1];
    float* out = (float*)d_out;

    cudaFuncSetAttribute(k_gemm_mma, cudaFuncAttributeMaxDynamicSharedMemorySize, GEMM_SMEM);

    k_mean<<<CC, 256>>>(T);
    k_norm<<<NBATCH * SN, 256>>>(I, T);
    dim3 gg(SN / 128, SN / 128, NBATCH);
    k_gemm_mma<<<gg, 256, GEMM_SMEM>>>();
    k_init_colmax<<<(NBATCH * SN + 255) / 256, 256>>>();
    k_rowstats<<<NBATCH * SN, 256>>>();
    k_colmax<<<dim3(SN / 256, SN / ICH, NBATCH), 256>>>();
    k_final<<<1, 256>>>(out);
}

// round 4
// speedup vs baseline: 4.9710x; 2.2715x over previous
#include <cuda_runtime.h>
#include <cuda_fp16.h>
#include <math.h>
#include <stdint.h>

#define SN 6400
#define CC 256
#define NBATCH 2

// ---------------- scratch (device globals; no allocation allowed) ----------
__device__ __align__(16) __half g_A[NBATCH * SN * CC];   // normalized I, fp16, [n][s][c]
__device__ __align__(16) __half g_B[NBATCH * SN * CC];   // normalized T, fp16, [n][s][c]
__device__ float    g_raw[(size_t)NBATCH * SN * SN];     // raw distance matrix
__device__ float    g_mean[CC];
__device__ unsigned g_colmax[NBATCH * SN];               // encoded float max

// order-preserving float <-> uint encoding (atomicMax on floats)
__device__ __forceinline__ unsigned enc_f(float f) {
    unsigned u = __float_as_uint(f);
    return (u & 0x80000000u) ? ~u : (u | 0x80000000u);
}
__device__ __forceinline__ float dec_f(unsigned u) {
    u = (u & 0x80000000u) ? (u ^ 0x80000000u) : ~u;
    return __uint_as_float(u);
}

// ---------------- PTX helpers (plain sm_80-era, no arch-variant gating) ----
__device__ __forceinline__ uint32_t smem_u32(const void* p) {
    uint32_t a;
    asm("{ .reg .u64 t; cvta.to.shared.u64 t, %1; cvt.u32.u64 %0, t; }" : "=r"(a) : "l"(p));
    return a;
}
__device__ __forceinline__ void cp16(uint32_t dst, const void* src) {
    asm volatile("cp.async.cg.shared.global [%0], [%1], 16;" :: "r"(dst), "l"(src));
}
#define CP_COMMIT() asm volatile("cp.async.commit_group;" ::: "memory")
#define CP_WAIT1()  asm volatile("cp.async.wait_group 1;" ::: "memory")

__device__ __forceinline__ void ldsm4(uint32_t r[4], uint32_t a) {
    asm volatile("ldmatrix.sync.aligned.m8n8.x4.shared.b16 {%0,%1,%2,%3}, [%4];"
        : "=r"(r[0]), "=r"(r[1]), "=r"(r[2]), "=r"(r[3]) : "r"(a));
}
__device__ __forceinline__ void mma_f16(float d[4], const uint32_t a[4],
                                        uint32_t b0, uint32_t b1) {
    asm volatile("mma.sync.aligned.m16n8k16.row.col.f32.f16.f16.f32 "
        "{%0,%1,%2,%3}, {%4,%5,%6,%7}, {%8,%9}, {%0,%1,%2,%3};"
        : "+f"(d[0]), "+f"(d[1]), "+f"(d[2]), "+f"(d[3])
        : "r"(a[0]), "r"(a[1]), "r"(a[2]), "r"(a[3]), "r"(b0), "r"(b1));
}
// SW128 xor swizzle for 128B rows: bits[6:4] ^= bits[9:7]
__device__ __forceinline__ uint32_t sw128(uint32_t o) {
    return o ^ (((o >> 7) & 7u) << 4);
}

// ---------------- kernel 1: per-channel mean of T over (n,h,w) -------------
__global__ void k_mean(const float* __restrict__ T) {
    int c = blockIdx.x;
    float s = 0.f;
    const float* p0 = T + (size_t)c * SN;
    const float* p1 = T + (size_t)(CC + c) * SN;
    for (int idx = threadIdx.x; idx < SN; idx += 256) s += p0[idx] + p1[idx];
    __shared__ float sh[256];
    sh[threadIdx.x] = s;
    __syncthreads();
    for (int o = 128; o > 0; o >>= 1) {
        if (threadIdx.x < o) sh[threadIdx.x] += sh[threadIdx.x + o];
        __syncthreads();
    }
    if (threadIdx.x == 0) g_mean[c] = sh[0] * (1.f / (NBATCH * SN));
}

// ---------------- kernel 2: center, normalize, fp16 output (coalesced) -----
// block handles 32 s-positions x 256 channels, via smem transpose tile
__global__ void __launch_bounds__(256) k_norm(const float* __restrict__ I,
                                              const float* __restrict__ T) {
    __shared__ float smI[256][33];
    __shared__ float smT[256][33];
    __shared__ float part[2][32][8];
    __shared__ float rs[32][2];

    int n  = blockIdx.y;
    int s0 = blockIdx.x * 32;
    int tid = threadIdx.x;

    // coalesced load: 32 consecutive s per channel row
#pragma unroll
    for (int it = 0; it < 32; it++) {
        int e = tid + it * 256;            // 0..8191
        int c = e >> 5;
        int s = e & 31;
        float m = g_mean[c];
        size_t ga = ((size_t)n * CC + c) * SN + s0 + s;
        smI[c][s] = I[ga] - m;
        smT[c][s] = T[ga] - m;
    }
    __syncthreads();

    // sum of squares over c: 8 threads per s, 32 c each
    {
        int s = tid & 31;
        int p = tid >> 5;                  // 0..7
        float si = 0.f, st = 0.f;
#pragma unroll
        for (int q = 0; q < 32; q++) {
            int c = p * 32 + q;
            float a = smI[c][s];
            float b = smT[c][s];
            si += a * a;
            st += b * b;
        }
        part[0][s][p] = si;
        part[1][s][p] = st;
    }
    __syncthreads();
    if (tid < 32) {
        float si = 0.f, st = 0.f;
#pragma unroll
        for (int p = 0; p < 8; p++) { si += part[0][tid][p]; st += part[1][tid][p]; }
        rs[tid][0] = rsqrtf(si);
        rs[tid][1] = rsqrtf(st);
    }
    __syncthreads();

    // coalesced fp16 writes: [s][c] layout, c contiguous
#pragma unroll
    for (int it = 0; it < 16; it++) {
        int e = tid + it * 256;            // 0..4095 : (s, cpair)
        int s  = e >> 7;
        int cp = (e & 127) * 2;
        float ri = rs[s][0];
        float rt = rs[s][1];
        size_t ob = ((size_t)n * SN + s0 + s) * CC + cp;
        *(__half2*)(g_A + ob) = __floats2half2_rn(smI[cp][s] * ri, smI[cp + 1][s] * ri);
        *(__half2*)(g_B + ob) = __floats2half2_rn(smT[cp][s] * rt, smT[cp + 1][s] * rt);
    }
}

// ---------------- kernel 3: fp16 mma.sync GEMM, raw = clip((1-cos)/2,0) ----
// CTA tile 128x128, BK=64 (128B rows, SW128), double-buffered cp.async
#define TILE_B 16384               // 128 rows x 128 bytes
#define STAGE_B (2 * TILE_B)       // A, B
#define GEMM_SMEM (2 * STAGE_B)    // 64 KB

__global__ void __launch_bounds__(256, 2) k_gemm_mma() {
    extern __shared__ __align__(1024) char smb[];
    int tid = threadIdx.x;
    int wid = tid >> 5;
    int l   = tid & 31;
    int n  = blockIdx.z;
    int i0 = blockIdx.y * 128;
    int j0 = blockIdx.x * 128;
    uint32_t sbase = smem_u32(smb);

    auto load_stage = [&](int kc, int s) {
        int k0 = kc * 64;
        uint32_t b = sbase + s * STAGE_B;
#pragma unroll
        for (int i = 0; i < 4; i++) {
            int e   = tid + i * 256;       // 0..1023
            int row = e >> 3;
            int ch  = e & 7;
            uint32_t so = sw128((uint32_t)(row * 128 + ch * 16));
            cp16(b + so,          g_A + (size_t)(n * SN + i0 + row) * CC + k0 + ch * 8);
            cp16(b + TILE_B + so, g_B + (size_t)(n * SN + j0 + row) * CC + k0 + ch * 8);
        }
        CP_COMMIT();
    };

    float acc[2][8][4];
#pragma unroll
    for (int a = 0; a < 2; a++)
#pragma unroll
        for (int g = 0; g < 8; g++)
#pragma unroll
            for (int q = 0; q < 4; q++) acc[a][g][q] = 0.f;

    int wm = wid >> 1;                 // 0..3
    int wn = wid & 1;                  // 0..1
    int mb = wm * 32;
    int nb = wn * 64;

    int a_row0 = mb + (l & 15);
    int a_ch   = l >> 4;
    int b_ch   = (l >> 3) & 1;
    int b_rowq = nb + (l & 7) + ((l >> 4) << 3);

    load_stage(0, 0);
    load_stage(1, 1);

    for (int kc = 0; kc < 4; kc++) {
        CP_WAIT1();
        __syncthreads();
        uint32_t b = sbase + (kc & 1) * STAGE_B;
#pragma unroll
        for (int ks = 0; ks < 4; ks++) {
            uint32_t ah[2][4], bt[4][4];
#pragma unroll
            for (int mt = 0; mt < 2; mt++) {
                uint32_t off = sw128((uint32_t)((a_row0 + mt * 16) * 128 + ks * 32 + a_ch * 16));
                ldsm4(ah[mt], b + off);
            }
#pragma unroll
            for (int ng = 0; ng < 4; ng++) {
                uint32_t off = sw128((uint32_t)((b_rowq + ng * 16) * 128 + ks * 32 + b_ch * 16));
                ldsm4(bt[ng], b + TILE_B + off);
            }
#pragma unroll
            for (int mt = 0; mt < 2; mt++)
#pragma unroll
                for (int ng = 0; ng < 4; ng++) {
                    mma_f16(acc[mt][2 * ng],     ah[mt], bt[ng][0], bt[ng][1]);
                    mma_f16(acc[mt][2 * ng + 1], ah[mt], bt[ng][2], bt[ng][3]);
                }
        }
        __syncthreads();
        if (kc + 2 < 4) load_stage(kc + 2, kc & 1);
        else            CP_COMMIT();
    }

    // ---- epilogue: raw = clip((1-cos)/2, 0) ----
    float* out = g_raw + (size_t)n * SN * SN;
    int r0 = i0 + mb + (l >> 2);
    int c0 = j0 + nb + (l & 3) * 2;
#pragma unroll
    for (int mt = 0; mt < 2; mt++)
#pragma unroll
        for (int g = 0; g < 8; g++) {
            int r = r0 + mt * 16;
            int c = c0 + g * 8;
            float2 v0, v1;
            v0.x = fmaxf(0.5f * (1.f - acc[mt][g][0]), 0.f);
            v0.y = fmaxf(0.5f * (1.f - acc[mt][g][1]), 0.f);
            v1.x = fmaxf(0.5f * (1.f - acc[mt][g][2]), 0.f);
            v1.y = fmaxf(0.5f * (1.f - acc[mt][g][3]), 0.f);
            *(float2*)(out + (size_t)r * SN + c)       = v0;
            *(float2*)(out + (size_t)(r + 8) * SN + c) = v1;
        }
}

// ---------------- kernel 4a: init colmax ----------------------------------
__global__ void k_init_colmax() {
    int idx = blockIdx.x * 256 + threadIdx.x;
    if (idx < NBATCH * SN) g_colmax[idx] = enc_f(-1e30f);
}

// ---------------- kernel 4b: fused row stats + column max ------------------
// block owns 32 rows; thread owns 25 fixed columns (register-resident).
// per row: rmin -> a = 10/(rmin+eps); m_j = 10 - a*raw; Z = sum exp(m);
// colmax_j = max over rows of (m_j - ln Z).  single pass over g_raw.
#define RPB 32
__global__ void __launch_bounds__(256) k_stats() {
    __shared__ float redm[8];
    __shared__ float redz[8];
    __shared__ float bc[2];

    int tid  = threadIdx.x;
    int lane = tid & 31;
    int warp = tid >> 5;
    int rbase = blockIdx.x * RPB;          // global row id in [0, NBATCH*SN)
    int n = rbase / SN;

    float cm[25];
#pragma unroll
    for (int q = 0; q < 25; q++) cm[q] = -1e30f;

    for (int r = 0; r < RPB; r++) {
        const float* row = g_raw + (size_t)(rbase + r) * SN;
        float v[25];
        float mn = 1e30f;
#pragma unroll
        for (int q = 0; q < 25; q++) {
            v[q] = row[tid + q * 256];
            mn = fminf(mn, v[q]);
        }
#pragma unroll
        for (int o = 16; o > 0; o >>= 1) mn = fminf(mn, __shfl_xor_sync(~0u, mn, o));
        if (lane == 0) redm[warp] = mn;
        __syncthreads();
        if (tid == 0) {
            float m = redm[0];
#pragma unroll
            for (int w = 1; w < 8; w++) m = fminf(m, redm[w]);
            bc[0] = 10.f / (m + 1e-5f);
        }
        __syncthreads();
        float a = bc[0];

        float z = 0.f;
#pragma unroll
        for (int q = 0; q < 25; q++) {
            v[q] = 10.f - a * v[q];        // m_j
            z += __expf(v[q]);
        }
#pragma unroll
        for (int o = 16; o > 0; o >>= 1) z += __shfl_xor_sync(~0u, z, o);
        if (lane == 0) redz[warp] = z;
        __syncthreads();
        if (tid == 0) {
            float s = 0.f;
#pragma unroll
            for (int w = 0; w < 8; w++) s += redz[w];
            bc[1] = __logf(s);
        }
        __syncthreads();
        float lnZ = bc[1];
#pragma unroll
        for (int q = 0; q < 25; q++) cm[q] = fmaxf(cm[q], v[q] - lnZ);
        __syncthreads();
    }

#pragma unroll
    for (int q = 0; q < 25; q++)
        atomicMax(&g_colmax[n * SN + ((rbase % SN) ? 0 : 0) + tid + q * 256], enc_f(cm[q]));
}

// ---------------- kernel 5: final reduction -> loss ------------------------
__global__ void k_final(float* __restrict__ out) {
    __shared__ float2 sh[256];
    int tid = threadIdx.x;
    float s0 = 0.f, s1 = 0.f;
    for (int j = tid; j < SN; j += 256) {
        s0 += __expf(dec_f(g_colmax[j]));
        s1 += __expf(dec_f(g_colmax[SN + j]));
    }
    sh[tid] = make_float2(s0, s1);
    __syncthreads();
    for (int o = 128; o > 0; o >>= 1) {
        if (tid < o) { sh[tid].x += sh[tid + o].x; sh[tid].y += sh[tid + o].y; }
        __syncthreads();
    }
    if (tid == 0) {
        float cs0 = sh[0].x * (1.f / SN);
        float cs1 = sh[0].y * (1.f / SN);
        out[0] = -0.5f * (logf(cs0) + logf(cs1));
    }
}

// ---------------- launcher --------------------------------------------------
extern "C" void kernel_launch(void* const* d_in, const int* in_sizes, int n_in,
                              void* d_out, int out_size) {
    const float* I = (const float*)d_in[0];
    const float* T = (const float*)d_in[1];
    float* out = (float*)d_out;

    cudaFuncSetAttribute(k_gemm_mma, cudaFuncAttributeMaxDynamicSharedMemorySize, GEMM_SMEM);

    k_mean<<<CC, 256>>>(T);
    k_norm<<<dim3(SN / 32, NBATCH), 256>>>(I, T);
    dim3 gg(SN / 128, SN / 128, NBATCH);
    k_gemm_mma<<<gg, 256, GEMM_SMEM>>>();
    k_init_colmax<<<(NBATCH * SN + 255) / 256, 256>>>();
    k_stats<<<NBATCH * SN / RPB, 256>>>();
    k_final<<<1, 256>>>(out);
}

// round 5
// speedup vs baseline: 5.3932x; 1.0849x over previous
#include <cuda_runtime.h>
#include <cuda_fp16.h>
#include <math.h>
#include <stdint.h>

#define SN 6400
#define CC 256
#define NBATCH 2

// ---------------- scratch (device globals; no allocation allowed) ----------
__device__ __align__(16) __half g_A[NBATCH * SN * CC];    // normalized I, fp16
__device__ __align__(16) __half g_B[NBATCH * SN * CC];    // normalized T, fp16
__device__ __align__(16) __half g_rawh[(size_t)NBATCH * SN * SN]; // raw matrix fp16
__device__ float    g_mean[CC];
__device__ unsigned g_colmax[NBATCH * SN];                // encoded float max

// order-preserving float <-> uint encoding (atomicMax on floats)
__device__ __forceinline__ unsigned enc_f(float f) {
    unsigned u = __float_as_uint(f);
    return (u & 0x80000000u) ? ~u : (u | 0x80000000u);
}
__device__ __forceinline__ float dec_f(unsigned u) {
    u = (u & 0x80000000u) ? (u ^ 0x80000000u) : ~u;
    return __uint_as_float(u);
}

// ---------------- PTX helpers (plain sm_80-era, no arch-variant gating) ----
__device__ __forceinline__ uint32_t smem_u32(const void* p) {
    uint32_t a;
    asm("{ .reg .u64 t; cvta.to.shared.u64 t, %1; cvt.u32.u64 %0, t; }" : "=r"(a) : "l"(p));
    return a;
}
__device__ __forceinline__ void cp16(uint32_t dst, const void* src) {
    asm volatile("cp.async.cg.shared.global [%0], [%1], 16;" :: "r"(dst), "l"(src));
}
#define CP_COMMIT() asm volatile("cp.async.commit_group;" ::: "memory")
#define CP_WAIT2()  asm volatile("cp.async.wait_group 2;" ::: "memory")

__device__ __forceinline__ void ldsm4(uint32_t r[4], uint32_t a) {
    asm volatile("ldmatrix.sync.aligned.m8n8.x4.shared.b16 {%0,%1,%2,%3}, [%4];"
        : "=r"(r[0]), "=r"(r[1]), "=r"(r[2]), "=r"(r[3]) : "r"(a));
}
__device__ __forceinline__ void mma_f16(float d[4], const uint32_t a[4],
                                        uint32_t b0, uint32_t b1) {
    asm volatile("mma.sync.aligned.m16n8k16.row.col.f32.f16.f16.f32 "
        "{%0,%1,%2,%3}, {%4,%5,%6,%7}, {%8,%9}, {%0,%1,%2,%3};"
        : "+f"(d[0]), "+f"(d[1]), "+f"(d[2]), "+f"(d[3])
        : "r"(a[0]), "r"(a[1]), "r"(a[2]), "r"(a[3]), "r"(b0), "r"(b1));
}
// SW128 xor swizzle for 128B rows: bits[6:4] ^= bits[9:7]
__device__ __forceinline__ uint32_t sw128(uint32_t o) {
    return o ^ (((o >> 7) & 7u) << 4);
}

// ---------------- kernel 1: per-channel mean of T over (n,h,w) -------------
__global__ void k_mean(const float* __restrict__ T) {
    int c = blockIdx.x;
    float s = 0.f;
    const float* p0 = T + (size_t)c * SN;
    const float* p1 = T + (size_t)(CC + c) * SN;
    for (int idx = threadIdx.x; idx < SN; idx += 256) s += p0[idx] + p1[idx];
    __shared__ float sh[256];
    sh[threadIdx.x] = s;
    __syncthreads();
    for (int o = 128; o > 0; o >>= 1) {
        if (threadIdx.x < o) sh[threadIdx.x] += sh[threadIdx.x + o];
        __syncthreads();
    }
    if (threadIdx.x == 0) g_mean[c] = sh[0] * (1.f / (NBATCH * SN));
}

// ---------------- kernel 2: center, normalize, fp16 output (coalesced) -----
__global__ void __launch_bounds__(256) k_norm(const float* __restrict__ I,
                                              const float* __restrict__ T) {
    __shared__ float smI[256][33];
    __shared__ float smT[256][33];
    __shared__ float part[2][32][8];
    __shared__ float rs[32][2];

    int n  = blockIdx.y;
    int s0 = blockIdx.x * 32;
    int tid = threadIdx.x;

#pragma unroll
    for (int it = 0; it < 32; it++) {
        int e = tid + it * 256;
        int c = e >> 5;
        int s = e & 31;
        float m = g_mean[c];
        size_t ga = ((size_t)n * CC + c) * SN + s0 + s;
        smI[c][s] = I[ga] - m;
        smT[c][s] = T[ga] - m;
    }
    __syncthreads();
    {
        int s = tid & 31;
        int p = tid >> 5;
        float si = 0.f, st = 0.f;
#pragma unroll
        for (int q = 0; q < 32; q++) {
            int c = p * 32 + q;
            float a = smI[c][s];
            float b = smT[c][s];
            si += a * a;
            st += b * b;
        }
        part[0][s][p] = si;
        part[1][s][p] = st;
    }
    __syncthreads();
    if (tid < 32) {
        float si = 0.f, st = 0.f;
#pragma unroll
        for (int p = 0; p < 8; p++) { si += part[0][tid][p]; st += part[1][tid][p]; }
        rs[tid][0] = rsqrtf(si);
        rs[tid][1] = rsqrtf(st);
    }
    __syncthreads();
#pragma unroll
    for (int it = 0; it < 16; it++) {
        int e = tid + it * 256;
        int s  = e >> 7;
        int cp = (e & 127) * 2;
        float ri = rs[s][0];
        float rt = rs[s][1];
        size_t ob = ((size_t)n * SN + s0 + s) * CC + cp;
        *(__half2*)(g_A + ob) = __floats2half2_rn(smI[cp][s] * ri, smI[cp + 1][s] * ri);
        *(__half2*)(g_B + ob) = __floats2half2_rn(smT[cp][s] * rt, smT[cp + 1][s] * rt);
    }
}

// ---------------- kernel 3: fp16 mma GEMM, rawh = clip((1-cos)/2,0) --------
// CTA tile 128x128, BK=64 (128B rows, SW128), 3-stage cp.async pipeline
#define TILE_B 16384               // 128 rows x 128 bytes
#define STAGE_B (2 * TILE_B)       // A, B
#define NSTAGE 3
#define GEMM_SMEM (NSTAGE * STAGE_B)   // 96 KB

__global__ void __launch_bounds__(256, 2) k_gemm_mma() {
    extern __shared__ __align__(1024) char smb[];
    int tid = threadIdx.x;
    int wid = tid >> 5;
    int l   = tid & 31;
    int n  = blockIdx.z;
    int i0 = blockIdx.y * 128;
    int j0 = blockIdx.x * 128;
    uint32_t sbase = smem_u32(smb);

    auto load_stage = [&](int kc, int s) {
        int k0 = kc * 64;
        uint32_t b = sbase + s * STAGE_B;
#pragma unroll
        for (int i = 0; i < 4; i++) {
            int e   = tid + i * 256;
            int row = e >> 3;
            int ch  = e & 7;
            uint32_t so = sw128((uint32_t)(row * 128 + ch * 16));
            cp16(b + so,          g_A + (size_t)(n * SN + i0 + row) * CC + k0 + ch * 8);
            cp16(b + TILE_B + so, g_B + (size_t)(n * SN + j0 + row) * CC + k0 + ch * 8);
        }
        CP_COMMIT();
    };

    float acc[2][8][4];
#pragma unroll
    for (int a = 0; a < 2; a++)
#pragma unroll
        for (int g = 0; g < 8; g++)
#pragma unroll
            for (int q = 0; q < 4; q++) acc[a][g][q] = 0.f;

    int wm = wid >> 1;
    int wn = wid & 1;
    int mb = wm * 32;
    int nb = wn * 64;

    int a_row0 = mb + (l & 15);
    int a_ch   = l >> 4;
    int b_ch   = (l >> 3) & 1;
    int b_rowq = nb + (l & 7) + ((l >> 4) << 3);

    load_stage(0, 0);
    load_stage(1, 1);
    load_stage(2, 2);

#pragma unroll
    for (int kc = 0; kc < 4; kc++) {
        CP_WAIT2();
        __syncthreads();
        uint32_t b = sbase + (kc % NSTAGE) * STAGE_B;
#pragma unroll
        for (int ks = 0; ks < 4; ks++) {
            uint32_t ah[2][4], bt[4][4];
#pragma unroll
            for (int mt = 0; mt < 2; mt++) {
                uint32_t off = sw128((uint32_t)((a_row0 + mt * 16) * 128 + ks * 32 + a_ch * 16));
                ldsm4(ah[mt], b + off);
            }
#pragma unroll
            for (int ng = 0; ng < 4; ng++) {
                uint32_t off = sw128((uint32_t)((b_rowq + ng * 16) * 128 + ks * 32 + b_ch * 16));
                ldsm4(bt[ng], b + TILE_B + off);
            }
#pragma unroll
            for (int mt = 0; mt < 2; mt++)
#pragma unroll
                for (int ng = 0; ng < 4; ng++) {
                    mma_f16(acc[mt][2 * ng],     ah[mt], bt[ng][0], bt[ng][1]);
                    mma_f16(acc[mt][2 * ng + 1], ah[mt], bt[ng][2], bt[ng][3]);
                }
        }
        __syncthreads();
        if (kc + 3 < 4) load_stage(kc + 3, kc % NSTAGE);
        else            CP_COMMIT();       // keep group FIFO advancing
    }

    // ---- epilogue: rawh = clip((1-cos)/2, 0) as fp16 ----
    __half* out = g_rawh + (size_t)n * SN * SN;
    int r0 = i0 + mb + (l >> 2);
    int c0 = j0 + nb + (l & 3) * 2;
#pragma unroll
    for (int mt = 0; mt < 2; mt++)
#pragma unroll
        for (int g = 0; g < 8; g++) {
            int r = r0 + mt * 16;
            int c = c0 + g * 8;
            *(__half2*)(out + (size_t)r * SN + c) = __floats2half2_rn(
                fmaxf(0.5f * (1.f - acc[mt][g][0]), 0.f),
                fmaxf(0.5f * (1.f - acc[mt][g][1]), 0.f));
            *(__half2*)(out + (size_t)(r + 8) * SN + c) = __floats2half2_rn(
                fmaxf(0.5f * (1.f - acc[mt][g][2]), 0.f),
                fmaxf(0.5f * (1.f - acc[mt][g][3]), 0.f));
        }
}

// ---------------- kernel 4a: init colmax ----------------------------------
__global__ void k_init_colmax() {
    int idx = blockIdx.x * 256 + threadIdx.x;
    if (idx < NBATCH * SN) g_colmax[idx] = enc_f(-1e30f);
}

// ---------------- kernel 4b: fused row stats + column max (fp16 input) -----
// block = 320 threads owning 32 rows; thread owns 10 half2 (20 fixed columns).
#define RPB 32
__global__ void __launch_bounds__(320) k_stats() {
    __shared__ float red[10];
    __shared__ float bc[2];

    int tid  = threadIdx.x;
    int lane = tid & 31;
    int warp = tid >> 5;                 // 0..9
    int rbase = blockIdx.x * RPB;        // global row id
    int n = rbase / SN;

    float cm[20];
#pragma unroll
    for (int q = 0; q < 20; q++) cm[q] = -1e30f;

    for (int r = 0; r < RPB; r++) {
        const __half2* row = (const __half2*)g_rawh + (size_t)(rbase + r) * (SN / 2);
        float2 v[10];
        float mn = 1e30f;
#pragma unroll
        for (int q = 0; q < 10; q++) {
            v[q] = __half22float2(row[tid + q * 320]);
            mn = fminf(mn, fminf(v[q].x, v[q].y));
        }
#pragma unroll
        for (int o = 16; o > 0; o >>= 1) mn = fminf(mn, __shfl_xor_sync(~0u, mn, o));
        if (lane == 0) red[warp] = mn;
        __syncthreads();
        if (tid == 0) {
            float m = red[0];
#pragma unroll
            for (int w = 1; w < 10; w++) m = fminf(m, red[w]);
            bc[0] = 10.f / (m + 1e-5f);
        }
        __syncthreads();
        float a = bc[0];

        float z = 0.f;
#pragma unroll
        for (int q = 0; q < 10; q++) {
            v[q].x = 10.f - a * v[q].x;
            v[q].y = 10.f - a * v[q].y;
            z += __expf(v[q].x) + __expf(v[q].y);
        }
#pragma unroll
        for (int o = 16; o > 0; o >>= 1) z += __shfl_xor_sync(~0u, z, o);
        if (lane == 0) red[warp] = z;
        __syncthreads();
        if (tid == 0) {
            float s = 0.f;
#pragma unroll
            for (int w = 0; w < 10; w++) s += red[w];
            bc[1] = __logf(s);
        }
        __syncthreads();
        float lnZ = bc[1];
#pragma unroll
        for (int q = 0; q < 10; q++) {
            cm[2 * q]     = fmaxf(cm[2 * q],     v[q].x - lnZ);
            cm[2 * q + 1] = fmaxf(cm[2 * q + 1], v[q].y - lnZ);
        }
        __syncthreads();
    }

#pragma unroll
    for (int q = 0; q < 10; q++) {
        int j = 2 * (tid + q * 320);
        atomicMax(&g_colmax[n * SN + j],     enc_f(cm[2 * q]));
        atomicMax(&g_colmax[n * SN + j + 1], enc_f(cm[2 * q + 1]));
    }
}

// ---------------- kernel 5: final reduction -> loss ------------------------
__global__ void k_final(float* __restrict__ out) {
    __shared__ float2 sh[256];
    int tid = threadIdx.x;
    float s0 = 0.f, s1 = 0.f;
    for (int j = tid; j < SN; j += 256) {
        s0 += __expf(dec_f(g_colmax[j]));
        s1 += __expf(dec_f(g_colmax[SN + j]));
    }
    sh[tid] = make_float2(s0, s1);
    __syncthreads();
    for (int o = 128; o > 0; o >>= 1) {
        if (tid < o) { sh[tid].x += sh[tid + o].x; sh[tid].y += sh[tid + o].y; }
        __syncthreads();
    }
    if (tid == 0) {
        float cs0 = sh[0].x * (1.f / SN);
        float cs1 = sh[0].y * (1.f / SN);
        out[0] = -0.5f * (logf(cs0) + logf(cs1));
    }
}

// ---------------- launcher --------------------------------------------------
extern "C" void kernel_launch(void* const* d_in, const int* in_sizes, int n_in,
                              void* d_out, int out_size) {
    const float* I = (const float*)d_in[0];
    const float* T = (const float*)d_in[1];
    float* out = (float*)d_out;

    cudaFuncSetAttribute(k_gemm_mma, cudaFuncAttributeMaxDynamicSharedMemorySize, GEMM_SMEM);

    k_mean<<<CC, 256>>>(T);
    k_norm<<<dim3(SN / 32, NBATCH), 256>>>(I, T);
    dim3 gg(SN / 128, SN / 128, NBATCH);
    k_gemm_mma<<<gg, 256, GEMM_SMEM>>>();
    k_init_colmax<<<(NBATCH * SN + 255) / 256, 256>>>();
    k_stats<<<NBATCH * SN / RPB, 320>>>();
    k_final<<<1, 256>>>(out);
}